// round 7
// baseline (speedup 1.0000x reference)
#include <cuda_runtime.h>
#include <cstdint>

// Problem constants: B=32, N=M=4096, d=3
#define BB     32
#define NPTS   4096
#define NCLUS  128
#define CSZ    32                 // targets per cluster (NPTS/NCLUS)
#define P3_TPB 256
#define P3_CPB (NPTS / P3_TPB)    // 16 CTAs per batch
#define NBLK   (BB * P3_CPB)      // 512 partial sums

#define BIGF 3.4028235e38f

// ---- persistent scratch (no allocations allowed) --------------------------
__device__ float4 g_tgtS [BB * NPTS];   // sorted targets {x, y, z, 0.5|t|^2}
__device__ float4 g_predS[BB * NPTS];   // sorted preds  {-x,-y,-z,  |p|^2}
__device__ float4 g_clusC[BB * NCLUS];  // cluster {cx, cy, cz, 0.5|c|^2}
__device__ float  g_clusR[BB * NCLUS];  // cluster radius (inflated)
__device__ float  g_bsum [NBLK];        // per-CTA partial sums

// ---------------------------------------------------------------------------
// P1: morton-key bitonic sort of one 4096-point array (per batch, per tensor).
// blockIdx.x: bit0 = isPred, rest = batch. Deterministic (keys are unique).
// ---------------------------------------------------------------------------
__device__ __forceinline__ unsigned morton18(float x, float y, float z) {
    int qx = min(max(__float2int_rd((x + 4.0f) * 8.0f), 0), 63);
    int qy = min(max(__float2int_rd((y + 4.0f) * 8.0f), 0), 63);
    int qz = min(max(__float2int_rd((z + 4.0f) * 8.0f), 0), 63);
    unsigned m = 0;
    #pragma unroll
    for (int b = 0; b < 6; b++) {
        m |= ((unsigned)((qx >> b) & 1)) << (3 * b + 2);
        m |= ((unsigned)((qy >> b) & 1)) << (3 * b + 1);
        m |= ((unsigned)((qz >> b) & 1)) << (3 * b + 0);
    }
    return m;
}

__global__ __launch_bounds__(512) void sort_kernel(const float* __restrict__ pred,
                                                   const float* __restrict__ tgt) {
    __shared__ unsigned sk[NPTS];   // 16 KB: (morton18 << 12) | idx
    int b      = blockIdx.x >> 1;
    int isPred = blockIdx.x & 1;
    const float* src = (isPred ? pred : tgt) + (size_t)b * NPTS * 3;
    int tid = threadIdx.x;

    for (int i = tid; i < NPTS; i += 512) {
        float x = src[3 * i], y = src[3 * i + 1], z = src[3 * i + 2];
        sk[i] = (morton18(x, y, z) << 12) | (unsigned)i;
    }

    for (int k = 2; k <= NPTS; k <<= 1) {
        for (int j = k >> 1; j > 0; j >>= 1) {
            __syncthreads();
            for (int t = tid; t < NPTS; t += 512) {
                int l = t ^ j;
                if (l > t) {
                    unsigned a = sk[t], c = sk[l];
                    bool up = ((t & k) == 0);
                    if ((a > c) == up) { sk[t] = c; sk[l] = a; }
                }
            }
        }
    }
    __syncthreads();

    float4* dst = (isPred ? g_predS : g_tgtS) + b * NPTS;
    for (int i = tid; i < NPTS; i += 512) {
        int si = (int)(sk[i] & 0xFFFu);
        float x = src[3 * si], y = src[3 * si + 1], z = src[3 * si + 2];
        float n2 = x * x + y * y + z * z;
        dst[i] = isPred ? make_float4(-x, -y, -z, n2)
                        : make_float4(x, y, z, 0.5f * n2);
    }
}

// ---------------------------------------------------------------------------
// P2: per-cluster centroid + bounding radius (one warp per cluster)
// ---------------------------------------------------------------------------
__global__ __launch_bounds__(128) void cluster_kernel() {
    int gw   = (blockIdx.x * 128 + threadIdx.x) >> 5;   // global warp id
    int lane = threadIdx.x & 31;
    int b = gw >> 7, k = gw & (NCLUS - 1);

    float4 t = g_tgtS[b * NPTS + k * CSZ + lane];
    float cx = t.x, cy = t.y, cz = t.z;
    #pragma unroll
    for (int o = 16; o; o >>= 1) {
        cx += __shfl_xor_sync(0xffffffffu, cx, o);
        cy += __shfl_xor_sync(0xffffffffu, cy, o);
        cz += __shfl_xor_sync(0xffffffffu, cz, o);
    }
    cx *= (1.0f / 32.0f); cy *= (1.0f / 32.0f); cz *= (1.0f / 32.0f);

    float dx = t.x - cx, dy = t.y - cy, dz = t.z - cz;
    float d2 = dx * dx + dy * dy + dz * dz;
    #pragma unroll
    for (int o = 16; o; o >>= 1)
        d2 = fmaxf(d2, __shfl_xor_sync(0xffffffffu, d2, o));

    if (lane == 0) {
        g_clusC[b * NCLUS + k] = make_float4(cx, cy, cz, 0.5f * (cx * cx + cy * cy + cz * cz));
        g_clusR[b * NCLUS + k] = sqrtf(d2) * 1.0005f + 1e-6f;
    }
}

// ---------------------------------------------------------------------------
// P3: branch-and-bound nearest-target per pred.
//   r(p,t) = 0.5|t|^2 - p.t  (3 FFMA);  d^2 = |p|^2 + 2 r
// Prune cluster iff |p-c|^2 > (u+rad)^2 (with conservative margin).
// ---------------------------------------------------------------------------
__global__ __launch_bounds__(P3_TPB) void chamfer_bb_kernel() {
    extern __shared__ float4 sT[];          // NPTS targets: 64 KB dynamic
    __shared__ float4 sC[NCLUS];
    __shared__ float  sR[NCLUS];
    __shared__ float  ssum[P3_TPB];

    int b     = blockIdx.x >> 4;            // P3_CPB = 16
    int chunk = blockIdx.x & 15;
    int tid   = threadIdx.x;

    const float4* gt = g_tgtS + b * NPTS;
    for (int i = tid; i < NPTS; i += P3_TPB) sT[i] = gt[i];
    if (tid < NCLUS) { sC[tid] = g_clusC[b * NCLUS + tid]; sR[tid] = g_clusR[b * NCLUS + tid]; }
    __syncthreads();

    int ip = chunk * P3_TPB + tid;          // pred rank within batch (sorted)
    float4 p = g_predS[b * NPTS + ip];      // {-x,-y,-z, p2}
    int k0 = ip >> 5;                       // positional probe cluster (warp-uniform)

    float mR = BIGF;
    {   // probe: full evaluation of k0
        const float4* ct = sT + k0 * CSZ;
        #pragma unroll 8
        for (int i = 0; i < CSZ; i++) {
            float4 t = ct[i];
            float r = __fmaf_rn(p.z, t.z, t.w);
            r = __fmaf_rn(p.y, t.y, r);
            r = __fmaf_rn(p.x, t.x, r);
            mR = fminf(mR, r);
        }
    }
    float u = sqrtf(fmaxf(__fmaf_rn(2.0f, mR, p.w), 0.0f));

    for (int k = 0; k < NCLUS; k++) {
        float4 c = sC[k];
        float rc = __fmaf_rn(p.z, c.z, c.w);
        rc = __fmaf_rn(p.y, c.y, rc);
        rc = __fmaf_rn(p.x, c.x, rc);
        float d2c = __fmaf_rn(2.0f, rc, p.w);              // |p-c|^2
        float s   = u + sR[k];
        // conservative keep test (margins dwarf fp rounding)
        bool keep = (k != k0) && (d2c <= __fmaf_rn(s * s, 1.0001f, 1e-6f));
        unsigned bal = __ballot_sync(0xffffffffu, keep);
        if (bal) {
            const float4* ct = sT + k * CSZ;
            #pragma unroll 8
            for (int i = 0; i < CSZ; i++) {
                float4 t = ct[i];
                float r = __fmaf_rn(p.z, t.z, t.w);
                r = __fmaf_rn(p.y, t.y, r);
                r = __fmaf_rn(p.x, t.x, r);
                mR = fminf(mR, r);
            }
            u = sqrtf(fmaxf(__fmaf_rn(2.0f, mR, p.w), 0.0f));
        }
    }

    // block-level deterministic sum of d = sqrt(max(p2 + 2 mR, 0))
    ssum[tid] = sqrtf(fmaxf(__fmaf_rn(2.0f, mR, p.w), 0.0f));
    __syncthreads();
    #pragma unroll
    for (int s = P3_TPB / 2; s > 0; s >>= 1) {
        if (tid < s) ssum[tid] += ssum[tid + s];
        __syncthreads();
    }
    if (tid == 0) g_bsum[blockIdx.x] = ssum[0];
}

// ---------------------------------------------------------------------------
// Final reduce: 512 partials -> mean
// ---------------------------------------------------------------------------
__global__ __launch_bounds__(NBLK) void reduce2_kernel(float* __restrict__ out) {
    __shared__ float ssum[NBLK];
    int tid = threadIdx.x;
    ssum[tid] = g_bsum[tid];
    __syncthreads();
    #pragma unroll
    for (int s = NBLK / 2; s > 0; s >>= 1) {
        if (tid < s) ssum[tid] += ssum[tid + s];
        __syncthreads();
    }
    if (tid == 0) out[0] = ssum[0] * (1.0f / (float)(BB * NPTS));
}

// ---------------------------------------------------------------------------
extern "C" void kernel_launch(void* const* d_in, const int* in_sizes, int n_in,
                              void* d_out, int out_size) {
    const float* pred   = (const float*)d_in[0];   // [B, N, 3]
    const float* target = (const float*)d_in[1];   // [B, M, 3]
    float* out = (float*)d_out;

    static bool attr_set = false;
    if (!attr_set) {
        cudaFuncSetAttribute(chamfer_bb_kernel,
                             cudaFuncAttributeMaxDynamicSharedMemorySize,
                             NPTS * (int)sizeof(float4));
        attr_set = true;
    }

    sort_kernel<<<BB * 2, 512>>>(pred, target);
    cluster_kernel<<<(BB * NCLUS * 32) / 128, 128>>>();
    chamfer_bb_kernel<<<NBLK, P3_TPB, NPTS * (int)sizeof(float4)>>>();
    reduce2_kernel<<<1, NBLK>>>(out);
}